// round 4
// baseline (speedup 1.0000x reference)
#include <cuda_runtime.h>
#include <cuda_bf16.h>
#include <mma.h>
using namespace nvcuda;

#define DM 16384
#define DS 512
#define DH 256
#define DG 768
#define DKE 320
#define DE 300
#define DC2 512

__device__ __align__(256) __nv_bfloat16 g_ehi[(size_t)DM*DKE], g_elo[(size_t)DM*DKE];
__device__ __align__(256) __nv_bfloat16 g_wihh[2ull*DG*DKE], g_wihl[2ull*DG*DKE];
__device__ __align__(256) __nv_bfloat16 g_whhh[2ull*DG*DH], g_whhl[2ull*DG*DH];
__device__ __align__(256) __nv_bfloat16 g_mwh[(size_t)DC2*DC2], g_mwl[(size_t)DC2*DC2];
__device__ __align__(256) float g_proj[2ull*DM*DG];      // gate-permuted
__device__ __align__(256) float g_ppad[2*DG];            // gate-permuted
__device__ __align__(256) float g_bihp[2*DG], g_bhhp[2*DG];
__device__ __align__(256) float g_h[2ull*DM*DH];
__device__ __align__(256) __nv_bfloat16 g_hhi[2][2ull*DM*DH], g_hlo[2][2ull*DM*DH];
__device__ __align__(256) float g_hidden[(size_t)DM*DC2];
__device__ __align__(256) __nv_bfloat16 g_nhi[(size_t)DM*DC2], g_nlo[(size_t)DM*DC2];
__device__ __align__(256) float g_mlp[(size_t)DM*DC2];
__device__ __align__(256) float g_bns[128*DC2], g_bnq[128*DC2];
__device__ __align__(256) float g_scale[DC2], g_shift[DC2];
__device__ __align__(256) float g_pool[32*DC2];

__device__ __forceinline__ void cp16(void* s, const void* g) {
    unsigned a = (unsigned)__cvta_generic_to_shared(s);
    asm volatile("cp.async.cg.shared.global [%0], [%1], 16;\n" :: "r"(a), "l"(g));
}
__device__ __forceinline__ void spl(float v, __nv_bfloat16* hi, __nv_bfloat16* lo) {
    __nv_bfloat16 h = __float2bfloat16(v);
    *hi = h; *lo = __float2bfloat16(v - __bfloat162float(h));
}
__device__ __forceinline__ float sigf(float x) { return 1.f / (1.f + __expf(-x)); }
// packed p -> original gate row g
__device__ __forceinline__ int permg(int p) {
    int bb = p / 192, r = p % 192, t = r / 64, i = r & 63;
    return t*256 + bb*64 + i;
}

// ---------- prep ----------
__global__ void prep_w(const float* wf, const float* hf, const float* bif, const float* bhf,
                       const float* wb, const float* hb, const float* bib, const float* bhb) {
    int b = blockIdx.x; int dir = b / DG, p = b % DG; int k = threadIdx.x;
    int g = permg(p);
    const float* wi = dir ? wb : wf; const float* wh = dir ? hb : hf;
    float v = (k < DE) ? wi[(size_t)g*DE + k] : 0.f;
    size_t o = ((size_t)dir*DG + p)*DKE + k;
    spl(v, &g_wihh[o], &g_wihl[o]);
    if (k < DH) {
        size_t o2 = ((size_t)dir*DG + p)*DH + k;
        spl(wh[(size_t)g*DH + k], &g_whhh[o2], &g_whhl[o2]);
    }
    if (k == 0) {
        g_bihp[dir*DG + p] = (dir ? bib : bif)[g];
        g_bhhp[dir*DG + p] = (dir ? bhb : bhf)[g];
    }
}
__global__ void prep_mlp(const float* mw) {
    size_t i = (size_t)blockIdx.x*DC2 + threadIdx.x;
    spl(mw[i], &g_mwh[i], &g_mwl[i]);
}
__global__ void pad_projk(const float* wf, const float* wb, const float* emb) {
    int idx = blockIdx.x*256 + threadIdx.x;
    int dir = idx / DG, p = idx % DG;
    int g = permg(p);
    const float* wi = dir ? wb : wf;
    float a = 0.f;
    for (int e = 0; e < DE; ++e) a += wi[(size_t)g*DE + e] * emb[e];
    g_ppad[idx] = a;
}
__global__ void gather_emb(const int* x, const float* emb) {
    int m = blockIdx.x, k = threadIdx.x;
    int tok = x[m];
    float v = (k < DE) ? emb[(size_t)tok*DE + k] : 0.f;
    spl(v, &g_ehi[(size_t)m*DKE + k], &g_elo[(size_t)m*DKE + k]);
}

// ---------- generic 3-split GEMM (proj / MLP): C = A @ B^T, 128x128 ----------
__global__ void __launch_bounds__(256) gemm3(int mode) {
    extern __shared__ __nv_bfloat16 sm[];
    const int SA = 128*40;
    const __nv_bfloat16 *Ah, *Al, *Bh, *Bl; float* C; int K, N;
    int z = blockIdx.z;
    if (mode == 0) { Ah = g_ehi; Al = g_elo;
        Bh = g_wihh + (size_t)z*DG*DKE; Bl = g_wihl + (size_t)z*DG*DKE;
        C = g_proj + (size_t)z*DM*DG; K = DKE; N = DG; }
    else { Ah = g_nhi; Al = g_nlo; Bh = g_mwh; Bl = g_mwl; C = g_mlp; K = DC2; N = DC2; }
    int m0 = blockIdx.x*128, n0 = blockIdx.y*128, t = threadIdx.x;
    int NK = K >> 5;
    wmma::fragment<wmma::accumulator,16,16,16,float> acc[4][2];
    #pragma unroll
    for (int i = 0; i < 4; ++i)
        #pragma unroll
        for (int j = 0; j < 2; ++j) wmma::fill_fragment(acc[i][j], 0.f);
    auto load = [&](int kc, int st) {
        __nv_bfloat16* b = sm + (size_t)st*4*SA;
        int k0 = kc*32;
        #pragma unroll
        for (int c = t; c < 512; c += 256) {
            int r = c >> 2, c8 = (c & 3)*8;
            cp16(b +        r*40 + c8, Ah + (size_t)(m0+r)*K + k0 + c8);
            cp16(b +   SA + r*40 + c8, Al + (size_t)(m0+r)*K + k0 + c8);
            cp16(b + 2*SA + r*40 + c8, Bh + (size_t)(n0+r)*K + k0 + c8);
            cp16(b + 3*SA + r*40 + c8, Bl + (size_t)(n0+r)*K + k0 + c8);
        }
        asm volatile("cp.async.commit_group;\n");
    };
    int w = t >> 5, wm = w & 1, wn = w >> 1;
    load(0, 0);
    for (int kc = 0; kc < NK; ++kc) {
        int st = kc & 1;
        if (kc + 1 < NK) { load(kc+1, st^1); asm volatile("cp.async.wait_group 1;\n"); }
        else             { asm volatile("cp.async.wait_group 0;\n"); }
        __syncthreads();
        const __nv_bfloat16 *pA = sm + (size_t)st*4*SA, *pAl = pA + SA,
                            *pB = pA + 2*SA, *pBl = pA + 3*SA;
        #pragma unroll
        for (int kk = 0; kk < 32; kk += 16) {
            wmma::fragment<wmma::matrix_a,16,16,16,__nv_bfloat16,wmma::row_major> fa[4], fal[4];
            wmma::fragment<wmma::matrix_b,16,16,16,__nv_bfloat16,wmma::col_major> fb[2], fbl[2];
            #pragma unroll
            for (int i = 0; i < 4; ++i) {
                wmma::load_matrix_sync(fa[i],  pA  + (wm*64 + i*16)*40 + kk, 40);
                wmma::load_matrix_sync(fal[i], pAl + (wm*64 + i*16)*40 + kk, 40);
            }
            #pragma unroll
            for (int j = 0; j < 2; ++j) {
                wmma::load_matrix_sync(fb[j],  pB  + (wn*32 + j*16)*40 + kk, 40);
                wmma::load_matrix_sync(fbl[j], pBl + (wn*32 + j*16)*40 + kk, 40);
            }
            #pragma unroll
            for (int i = 0; i < 4; ++i)
                #pragma unroll
                for (int j = 0; j < 2; ++j) {
                    wmma::mma_sync(acc[i][j], fa[i],  fb[j],  acc[i][j]);
                    wmma::mma_sync(acc[i][j], fal[i], fb[j],  acc[i][j]);
                    wmma::mma_sync(acc[i][j], fa[i],  fbl[j], acc[i][j]);
                }
        }
        __syncthreads();
    }
    #pragma unroll
    for (int i = 0; i < 4; ++i)
        #pragma unroll
        for (int j = 0; j < 2; ++j)
            wmma::store_matrix_sync(C + (size_t)(m0 + wm*64 + i*16)*N + n0 + wn*32 + j*16,
                                    acc[i][j], N, wmma::mem_row_major);
}

// ---------- fused step: hg = h @ Whhp^T (128x192 tile) + GRU epilogue ----------
__global__ void __launch_bounds__(384, 1) step_fused(int rbuf, int wbuf, int offF, int offB) {
    extern __shared__ __nv_bfloat16 sm[];
    const int SA = 128*40;              // 5120 elems
    const int SB = 192*40;              // 7680 elems
    const int STG = 2*SA + 2*SB;        // 25600 elems/stage
    int m0 = blockIdx.x*128, bb = blockIdx.y, dir = blockIdx.z;
    const __nv_bfloat16* Ah = g_hhi[rbuf] + (size_t)dir*DM*DH;
    const __nv_bfloat16* Al = g_hlo[rbuf] + (size_t)dir*DM*DH;
    const __nv_bfloat16* Bh = g_whhh + ((size_t)dir*DG + bb*192)*DH;
    const __nv_bfloat16* Bl = g_whhl + ((size_t)dir*DG + bb*192)*DH;
    int t = threadIdx.x;

    wmma::fragment<wmma::accumulator,16,16,16,float> acc[2][4];
    #pragma unroll
    for (int i = 0; i < 2; ++i)
        #pragma unroll
        for (int j = 0; j < 4; ++j) wmma::fill_fragment(acc[i][j], 0.f);

    auto load = [&](int kc, int st) {
        __nv_bfloat16* b = sm + (size_t)st*STG;
        int k0 = kc*32;
        for (int c = t; c < 512; c += 384) {
            int r = c >> 2, c8 = (c & 3)*8;
            cp16(b +      r*40 + c8, Ah + (size_t)(m0+r)*DH + k0 + c8);
            cp16(b + SA + r*40 + c8, Al + (size_t)(m0+r)*DH + k0 + c8);
        }
        for (int c = t; c < 768; c += 384) {
            int r = c >> 2, c8 = (c & 3)*8;
            cp16(b + 2*SA +      r*40 + c8, Bh + (size_t)r*DH + k0 + c8);
            cp16(b + 2*SA + SB + r*40 + c8, Bl + (size_t)r*DH + k0 + c8);
        }
        asm volatile("cp.async.commit_group;\n");
    };
    int w = t >> 5, wm = w & 3, wn = w >> 2;   // 4(m) x 3(n) warps
    load(0, 0);
    const int NK = DH/32;                       // 8
    for (int kc = 0; kc < NK; ++kc) {
        int st = kc & 1;
        if (kc + 1 < NK) { load(kc+1, st^1); asm volatile("cp.async.wait_group 1;\n"); }
        else             { asm volatile("cp.async.wait_group 0;\n"); }
        __syncthreads();
        const __nv_bfloat16 *pA = sm + (size_t)st*STG, *pAl = pA + SA,
                            *pB = pA + 2*SA, *pBl = pB + SB;
        #pragma unroll
        for (int kk = 0; kk < 32; kk += 16) {
            wmma::fragment<wmma::matrix_a,16,16,16,__nv_bfloat16,wmma::row_major> fa[2], fal[2];
            #pragma unroll
            for (int i = 0; i < 2; ++i) {
                wmma::load_matrix_sync(fa[i],  pA  + (wm*32 + i*16)*40 + kk, 40);
                wmma::load_matrix_sync(fal[i], pAl + (wm*32 + i*16)*40 + kk, 40);
            }
            #pragma unroll
            for (int j = 0; j < 4; ++j) {
                wmma::fragment<wmma::matrix_b,16,16,16,__nv_bfloat16,wmma::col_major> fb, fbl;
                wmma::load_matrix_sync(fb,  pB  + (wn*64 + j*16)*40 + kk, 40);
                wmma::load_matrix_sync(fbl, pBl + (wn*64 + j*16)*40 + kk, 40);
                #pragma unroll
                for (int i = 0; i < 2; ++i) {
                    wmma::mma_sync(acc[i][j], fa[i],  fb,  acc[i][j]);
                    wmma::mma_sync(acc[i][j], fal[i], fb,  acc[i][j]);
                    wmma::mma_sync(acc[i][j], fa[i],  fbl, acc[i][j]);
                }
            }
        }
        __syncthreads();
    }
    // stage accumulators (smem stages are dead now)
    float* sC = (float*)sm;                     // 128 x 200 fp32
    #pragma unroll
    for (int i = 0; i < 2; ++i)
        #pragma unroll
        for (int j = 0; j < 4; ++j)
            wmma::store_matrix_sync(sC + (wm*32 + i*16)*200 + wn*64 + j*16,
                                    acc[i][j], 200, wmma::mem_row_major);
    __syncthreads();

    // fused GRU epilogue: 128 rows x 64 channels
    int off = dir ? offB : offF;
    int i_ = t & 63;
    int dbase = dir*DG + bb*192;
    float bi0 = g_bihp[dbase + i_], bi1 = g_bihp[dbase + 64 + i_], bi2 = g_bihp[dbase + 128 + i_];
    float bh0 = g_bhhp[dbase + i_], bh1 = g_bhhp[dbase + 64 + i_], bh2 = g_bhhp[dbase + 128 + i_];
    size_t hb0 = ((size_t)dir*DM + m0)*DH + bb*64 + i_;
    for (int idx = t; idx < 8192; idx += 384) {
        int ml = idx >> 6;
        int m = m0 + ml;
        int s = m & (DS - 1);
        int j = s + off;
        const float* pr = (j >= 0 && j < DS)
            ? g_proj + ((size_t)dir*DM + m + off)*DG + bb*192
            : g_ppad + dbase;
        float xr = pr[i_] + bi0;
        float xz = pr[64 + i_] + bi1;
        float xn = pr[128 + i_] + bi2;
        float hr = sC[ml*200 + i_] + bh0;
        float hz = sC[ml*200 + 64 + i_] + bh1;
        float hn = sC[ml*200 + 128 + i_] + bh2;
        float r  = sigf(xr + hr);
        float zz = sigf(xz + hz);
        float n  = tanhf(xn + r*hn);
        size_t hidx = hb0 + (size_t)ml*DH;
        float hold = g_h[hidx];
        float hv = (1.f - zz)*n + zz*hold;
        g_h[hidx] = hv;
        spl(hv, &g_hhi[wbuf][hidx], &g_hlo[wbuf][hidx]);
    }
}

// ---------- step 0 (h=0, no GEMM), packed layout ----------
__global__ void gru0(int offF, int offB) {
    int m = blockIdx.x, dir = blockIdx.y, hh = threadIdx.x;
    int off = dir ? offB : offF;
    int s = m & (DS - 1);
    int j = s + off;
    int bb = hh >> 6, i_ = hh & 63;
    int dbase = dir*DG + bb*192;
    const float* pr = (j >= 0 && j < DS)
        ? g_proj + ((size_t)dir*DM + m + off)*DG + bb*192
        : g_ppad + dbase;
    float xr = pr[i_] + g_bihp[dbase + i_];
    float xz = pr[64 + i_] + g_bihp[dbase + 64 + i_];
    float xn = pr[128 + i_] + g_bihp[dbase + 128 + i_];
    float hr = g_bhhp[dbase + i_];
    float hz = g_bhhp[dbase + 64 + i_];
    float hn = g_bhhp[dbase + 128 + i_];
    float r  = sigf(xr + hr);
    float zz = sigf(xz + hz);
    float n  = tanhf(xn + r*hn);
    float hv = (1.f - zz)*n;
    size_t hidx = ((size_t)dir*DM + m)*DH + hh;
    g_h[hidx] = hv;
    spl(hv, &g_hhi[0][hidx], &g_hlo[0][hidx]);
}

// ---------- tail ----------
__global__ void concat_stats(const int* x) {
    int blk = blockIdx.x, c = threadIdx.x;
    float s1 = 0, q1 = 0, s2 = 0, q2 = 0;
    for (int r = 0; r < 128; ++r) {
        int m = blk*128 + r;
        float mk = (x[m] > 0) ? 1.f : 0.f;
        float a = g_h[(size_t)m*DH + c] * mk;
        float b = g_h[((size_t)DM + m)*DH + c] * mk;
        g_hidden[(size_t)m*DC2 + c] = a;
        g_hidden[(size_t)m*DC2 + DH + c] = b;
        s1 += a; q1 += a*a; s2 += b; q2 += b*b;
    }
    g_bns[blk*DC2 + c] = s1;      g_bnq[blk*DC2 + c] = q1;
    g_bns[blk*DC2 + DH + c] = s2; g_bnq[blk*DC2 + DH + c] = q2;
}
__global__ void bn_fin(const float* gam, const float* bet) {
    int c = threadIdx.x;
    float s = 0, q = 0;
    for (int b = 0; b < 128; ++b) { s += g_bns[b*DC2 + c]; q += g_bnq[b*DC2 + c]; }
    float mu = s / (float)DM;
    float var = q / (float)DM - mu*mu;
    float sc = gam[c] * rsqrtf(var + 1e-5f);
    g_scale[c] = sc; g_shift[c] = bet[c] - mu*sc;
}
__global__ void norm_split(const int* x) {
    int m = blockIdx.x, c = threadIdx.x;
    float mk = (x[m] > 0) ? 1.f : 0.f;
    float v = (g_hidden[(size_t)m*DC2 + c] * g_scale[c] + g_shift[c]) * mk;
    spl(v, &g_nhi[(size_t)m*DC2 + c], &g_nlo[(size_t)m*DC2 + c]);
}
__global__ void poolk(const int* x, const float* mb) {
    int b = blockIdx.x, c = threadIdx.x;
    float bias = mb[c], mx = -3.4e38f;
    for (int s = 0; s < DS; ++s) {
        int m = b*DS + s;
        float v = (x[m] > 0) ? g_mlp[(size_t)m*DC2 + c] + bias : -65500.f;
        mx = fmaxf(mx, v);
    }
    g_pool[b*DC2 + c] = mx;
}
__global__ void headk(const float* lw, const float* lb, float* out) {
    int b = blockIdx.x, w = threadIdx.x >> 5, l = threadIdx.x & 31;
    float s = 0;
    for (int i = l; i < DC2; i += 32) s += g_pool[b*DC2 + i] * lw[(size_t)w*DC2 + i];
    #pragma unroll
    for (int o = 16; o; o >>= 1) s += __shfl_xor_sync(~0u, s, o);
    if (!l) out[b*2 + w] = s + lb[w];
}

extern "C" void kernel_launch(void* const* d_in, const int* in_sizes, int n_in,
                              void* d_out, int out_size) {
    const int*   x    = (const int*)d_in[0];
    const float* emb  = (const float*)d_in[5];
    const float* wihf = (const float*)d_in[6];
    const float* whhf = (const float*)d_in[7];
    const float* bihf = (const float*)d_in[8];
    const float* bhhf = (const float*)d_in[9];
    const float* wihb = (const float*)d_in[10];
    const float* whhb = (const float*)d_in[11];
    const float* bihb = (const float*)d_in[12];
    const float* bhhb = (const float*)d_in[13];
    const float* gam  = (const float*)d_in[14];
    const float* bet  = (const float*)d_in[15];
    const float* mw   = (const float*)d_in[16];
    const float* mb   = (const float*)d_in[17];
    const float* lw   = (const float*)d_in[18];
    const float* lb   = (const float*)d_in[19];
    float* out = (float*)d_out;

    cudaFuncSetAttribute(gemm3, cudaFuncAttributeMaxDynamicSharedMemorySize, 81920);
    cudaFuncSetAttribute(step_fused, cudaFuncAttributeMaxDynamicSharedMemorySize, 102400);

    prep_w<<<2*DG, DKE>>>(wihf, whhf, bihf, bhhf, wihb, whhb, bihb, bhhb);
    prep_mlp<<<DC2, DC2>>>(mw);
    pad_projk<<<(2*DG)/256, 256>>>(wihf, wihb, emb);
    gather_emb<<<DM, DKE>>>(x, emb);

    gemm3<<<dim3(DM/128, DG/128, 2), 256, 81920>>>(0);   // proj (packed, both dirs)
    gru0<<<dim3(DM, 2), DH>>>(-14, 14);
    for (int i = 1; i < 15; ++i)
        step_fused<<<dim3(DM/128, 4, 2), 384, 102400>>>((i + 1) & 1, i & 1, i - 14, 14 - i);

    concat_stats<<<128, 256>>>(x);
    bn_fin<<<1, DC2>>>(gam, bet);
    norm_split<<<DM, DC2>>>(x);
    gemm3<<<dim3(DM/128, DC2/128, 1), 256, 81920>>>(1);  // MLP
    poolk<<<32, DC2>>>(x, mb);
    headk<<<32, 64>>>(lw, lb, out);
}

// round 6
// speedup vs baseline: 1.2312x; 1.2312x over previous
#include <cuda_runtime.h>
#include <cuda_bf16.h>
#include <mma.h>
#include <cstdint>
using namespace nvcuda;

#define DM 16384
#define DS 512
#define DH 256
#define DG 768
#define DKE 320
#define DE 300
#define DC2 512

__device__ __align__(256) __nv_bfloat16 g_ehi[(size_t)DM*DKE], g_elo[(size_t)DM*DKE];
__device__ __align__(256) __nv_bfloat16 g_wihh[2ull*DG*DKE], g_wihl[2ull*DG*DKE];
__device__ __align__(256) __nv_bfloat16 g_whhh[2ull*DG*DH], g_whhl[2ull*DG*DH];
__device__ __align__(256) __nv_bfloat16 g_mwh[(size_t)DC2*DC2], g_mwl[(size_t)DC2*DC2];
__device__ __align__(256) float g_proj[2ull*DM*DG];      // gate-permuted
__device__ __align__(256) float g_ppad[2*DG];
__device__ __align__(256) float g_bihp[2*DG], g_bhhp[2*DG];
__device__ __align__(256) float g_h[2ull*DM*DH];
__device__ __align__(256) __nv_bfloat16 g_hhi[2][2ull*DM*DH], g_hlo[2][2ull*DM*DH];
__device__ __align__(256) float g_hidden[(size_t)DM*DC2];
__device__ __align__(256) __nv_bfloat16 g_nhi[(size_t)DM*DC2], g_nlo[(size_t)DM*DC2];
__device__ __align__(256) float g_mlp[(size_t)DM*DC2];
__device__ __align__(256) float g_bns[128*DC2], g_bnq[128*DC2];
__device__ __align__(256) float g_scale[DC2], g_shift[DC2];
__device__ __align__(256) float g_pool[32*DC2];

__device__ __forceinline__ void cp16(void* s, const void* g) {
    unsigned a = (unsigned)__cvta_generic_to_shared(s);
    asm volatile("cp.async.cg.shared.global [%0], [%1], 16;\n" :: "r"(a), "l"(g));
}
__device__ __forceinline__ void spl(float v, __nv_bfloat16* hi, __nv_bfloat16* lo) {
    __nv_bfloat16 h = __float2bfloat16(v);
    *hi = h; *lo = __float2bfloat16(v - __bfloat162float(h));
}
__device__ __forceinline__ float sigf(float x) { return 1.f / (1.f + __expf(-x)); }
__device__ __forceinline__ int permg(int p) {
    int bb = p / 192, r = p % 192, t = r / 64, i = r & 63;
    return t*256 + bb*64 + i;
}

// ---------- prep ----------
__global__ void prep_w(const float* wf, const float* hf, const float* bif, const float* bhf,
                       const float* wb, const float* hb, const float* bib, const float* bhb) {
    int b = blockIdx.x; int dir = b / DG, p = b % DG; int k = threadIdx.x;
    int g = permg(p);
    const float* wi = dir ? wb : wf; const float* wh = dir ? hb : hf;
    float v = (k < DE) ? wi[(size_t)g*DE + k] : 0.f;
    size_t o = ((size_t)dir*DG + p)*DKE + k;
    spl(v, &g_wihh[o], &g_wihl[o]);
    if (k < DH) {
        size_t o2 = ((size_t)dir*DG + p)*DH + k;
        spl(wh[(size_t)g*DH + k], &g_whhh[o2], &g_whhl[o2]);
    }
    if (k == 0) {
        g_bihp[dir*DG + p] = (dir ? bib : bif)[g];
        g_bhhp[dir*DG + p] = (dir ? bhb : bhf)[g];
    }
}
__global__ void prep_mlp(const float* mw) {
    size_t i = (size_t)blockIdx.x*DC2 + threadIdx.x;
    spl(mw[i], &g_mwh[i], &g_mwl[i]);
}
__global__ void pad_projk(const float* wf, const float* wb, const float* emb) {
    int idx = blockIdx.x*256 + threadIdx.x;
    int dir = idx / DG, p = idx % DG;
    int g = permg(p);
    const float* wi = dir ? wb : wf;
    float a = 0.f;
    for (int e = 0; e < DE; ++e) a += wi[(size_t)g*DE + e] * emb[e];
    g_ppad[idx] = a;
}
__global__ void gather_emb(const int* x, const float* emb) {
    int m = blockIdx.x, k = threadIdx.x;
    int tok = x[m];
    float v = (k < DE) ? emb[(size_t)tok*DE + k] : 0.f;
    spl(v, &g_ehi[(size_t)m*DKE + k], &g_elo[(size_t)m*DKE + k]);
}

// ---------- generic 3-split wmma GEMM (proj / MLP): C = A @ B^T, 128x128 ----------
__global__ void __launch_bounds__(256) gemm3(int mode) {
    extern __shared__ __nv_bfloat16 sm[];
    const int SA = 128*40;
    const __nv_bfloat16 *Ah, *Al, *Bh, *Bl; float* C; int K, N;
    int z = blockIdx.z;
    if (mode == 0) { Ah = g_ehi; Al = g_elo;
        Bh = g_wihh + (size_t)z*DG*DKE; Bl = g_wihl + (size_t)z*DG*DKE;
        C = g_proj + (size_t)z*DM*DG; K = DKE; N = DG; }
    else { Ah = g_nhi; Al = g_nlo; Bh = g_mwh; Bl = g_mwl; C = g_mlp; K = DC2; N = DC2; }
    int m0 = blockIdx.x*128, n0 = blockIdx.y*128, t = threadIdx.x;
    int NK = K >> 5;
    wmma::fragment<wmma::accumulator,16,16,16,float> acc[4][2];
    #pragma unroll
    for (int i = 0; i < 4; ++i)
        #pragma unroll
        for (int j = 0; j < 2; ++j) wmma::fill_fragment(acc[i][j], 0.f);
    auto load = [&](int kc, int st) {
        __nv_bfloat16* b = sm + (size_t)st*4*SA;
        int k0 = kc*32;
        #pragma unroll
        for (int c = t; c < 512; c += 256) {
            int r = c >> 2, c8 = (c & 3)*8;
            cp16(b +        r*40 + c8, Ah + (size_t)(m0+r)*K + k0 + c8);
            cp16(b +   SA + r*40 + c8, Al + (size_t)(m0+r)*K + k0 + c8);
            cp16(b + 2*SA + r*40 + c8, Bh + (size_t)(n0+r)*K + k0 + c8);
            cp16(b + 3*SA + r*40 + c8, Bl + (size_t)(n0+r)*K + k0 + c8);
        }
        asm volatile("cp.async.commit_group;\n");
    };
    int w = t >> 5, wm = w & 1, wn = w >> 1;
    load(0, 0);
    for (int kc = 0; kc < NK; ++kc) {
        int st = kc & 1;
        if (kc + 1 < NK) { load(kc+1, st^1); asm volatile("cp.async.wait_group 1;\n"); }
        else             { asm volatile("cp.async.wait_group 0;\n"); }
        __syncthreads();
        const __nv_bfloat16 *pA = sm + (size_t)st*4*SA, *pAl = pA + SA,
                            *pB = pA + 2*SA, *pBl = pA + 3*SA;
        #pragma unroll
        for (int kk = 0; kk < 32; kk += 16) {
            wmma::fragment<wmma::matrix_a,16,16,16,__nv_bfloat16,wmma::row_major> fa[4], fal[4];
            wmma::fragment<wmma::matrix_b,16,16,16,__nv_bfloat16,wmma::col_major> fb[2], fbl[2];
            #pragma unroll
            for (int i = 0; i < 4; ++i) {
                wmma::load_matrix_sync(fa[i],  pA  + (wm*64 + i*16)*40 + kk, 40);
                wmma::load_matrix_sync(fal[i], pAl + (wm*64 + i*16)*40 + kk, 40);
            }
            #pragma unroll
            for (int j = 0; j < 2; ++j) {
                wmma::load_matrix_sync(fb[j],  pB  + (wn*32 + j*16)*40 + kk, 40);
                wmma::load_matrix_sync(fbl[j], pBl + (wn*32 + j*16)*40 + kk, 40);
            }
            #pragma unroll
            for (int i = 0; i < 4; ++i)
                #pragma unroll
                for (int j = 0; j < 2; ++j) {
                    wmma::mma_sync(acc[i][j], fa[i],  fb[j],  acc[i][j]);
                    wmma::mma_sync(acc[i][j], fal[i], fb[j],  acc[i][j]);
                    wmma::mma_sync(acc[i][j], fa[i],  fbl[j], acc[i][j]);
                }
        }
        __syncthreads();
    }
    #pragma unroll
    for (int i = 0; i < 4; ++i)
        #pragma unroll
        for (int j = 0; j < 2; ++j)
            wmma::store_matrix_sync(C + (size_t)(m0 + wm*64 + i*16)*N + n0 + wn*32 + j*16,
                                    acc[i][j], N, wmma::mem_row_major);
}

// ---------- fused step: 64x192x256 3-split wmma + GRU epilogue, 2 CTAs/SM ----------
// stage (bf16 elems): Ah[0,2560) Al[2560,5120) Bh[5120,12800) Bl[12800,20480)
// 2 stages = 40960 elems = 81920 B; epilogue sC (64x200 fp32 = 51200 B) reuses stages.
__global__ void __launch_bounds__(256, 2) step_fused(int rbuf, int wbuf, int offF, int offB) {
    extern __shared__ __nv_bfloat16 sm[];
    const int OAL = 2560, OBH = 5120, OBL = 12800, STG = 20480;
    int m0 = blockIdx.x*64, bb = blockIdx.y, dir = blockIdx.z;
    const __nv_bfloat16* Ah = g_hhi[rbuf] + (size_t)dir*DM*DH;
    const __nv_bfloat16* Al = g_hlo[rbuf] + (size_t)dir*DM*DH;
    const __nv_bfloat16* Bh = g_whhh + ((size_t)dir*DG + bb*192)*DH;
    const __nv_bfloat16* Bl = g_whhl + ((size_t)dir*DG + bb*192)*DH;
    int t = threadIdx.x;

    wmma::fragment<wmma::accumulator,16,16,16,float> acc[2][3];
    #pragma unroll
    for (int i = 0; i < 2; ++i)
        #pragma unroll
        for (int j = 0; j < 3; ++j) wmma::fill_fragment(acc[i][j], 0.f);

    auto load = [&](int kc, int st) {
        __nv_bfloat16* b = sm + st*STG;
        int k0 = kc*32;
        {   // A: 64 rows x 4 chunks = 256 cp16 per split -> 1 per thread
            int r = t >> 2, c8 = (t & 3)*8;
            cp16(b +       r*40 + c8, Ah + (size_t)(m0+r)*DH + k0 + c8);
            cp16(b + OAL + r*40 + c8, Al + (size_t)(m0+r)*DH + k0 + c8);
        }
        #pragma unroll
        for (int c = t; c < 768; c += 256) {   // B: 192 rows x 4 chunks
            int r = c >> 2, c8 = (c & 3)*8;
            cp16(b + OBH + r*40 + c8, Bh + (size_t)r*DH + k0 + c8);
            cp16(b + OBL + r*40 + c8, Bl + (size_t)r*DH + k0 + c8);
        }
        asm volatile("cp.async.commit_group;\n");
    };
    int w = t >> 5, wm = w & 1, wn = w >> 1;   // 2(m) x 4(n) warps, warp tile 32x48
    load(0, 0);
    const int NK = DH/32;                       // 8
    for (int kc = 0; kc < NK; ++kc) {
        int st = kc & 1;
        if (kc + 1 < NK) { load(kc+1, st^1); asm volatile("cp.async.wait_group 1;\n"); }
        else             { asm volatile("cp.async.wait_group 0;\n"); }
        __syncthreads();
        const __nv_bfloat16 *pA = sm + st*STG, *pAl = pA + OAL,
                            *pB = pA + OBH, *pBl = pA + OBL;
        #pragma unroll
        for (int kk = 0; kk < 32; kk += 16) {
            wmma::fragment<wmma::matrix_a,16,16,16,__nv_bfloat16,wmma::row_major> fa[2], fal[2];
            wmma::fragment<wmma::matrix_b,16,16,16,__nv_bfloat16,wmma::col_major> fb[3], fbl[3];
            #pragma unroll
            for (int i = 0; i < 2; ++i) {
                wmma::load_matrix_sync(fa[i],  pA  + (wm*32 + i*16)*40 + kk, 40);
                wmma::load_matrix_sync(fal[i], pAl + (wm*32 + i*16)*40 + kk, 40);
            }
            #pragma unroll
            for (int j = 0; j < 3; ++j) {
                wmma::load_matrix_sync(fb[j],  pB  + (wn*48 + j*16)*40 + kk, 40);
                wmma::load_matrix_sync(fbl[j], pBl + (wn*48 + j*16)*40 + kk, 40);
            }
            #pragma unroll
            for (int i = 0; i < 2; ++i)
                #pragma unroll
                for (int j = 0; j < 3; ++j) {
                    wmma::mma_sync(acc[i][j], fa[i],  fb[j],  acc[i][j]);
                    wmma::mma_sync(acc[i][j], fal[i], fb[j],  acc[i][j]);
                    wmma::mma_sync(acc[i][j], fa[i],  fbl[j], acc[i][j]);
                }
        }
        __syncthreads();
    }
    // stage accumulators into (now dead) stage smem
    float* sC = (float*)sm;                     // 64 x 200
    #pragma unroll
    for (int i = 0; i < 2; ++i)
        #pragma unroll
        for (int j = 0; j < 3; ++j)
            wmma::store_matrix_sync(sC + (wm*32 + i*16)*200 + wn*48 + j*16,
                                    acc[i][j], 200, wmma::mem_row_major);
    __syncthreads();

    // fused GRU epilogue: 64 rows x 64 channels
    int off = dir ? offB : offF;
    int i_ = t & 63;
    int dbase = dir*DG + bb*192;
    float bi0 = g_bihp[dbase + i_], bi1 = g_bihp[dbase + 64 + i_], bi2 = g_bihp[dbase + 128 + i_];
    float bh0 = g_bhhp[dbase + i_], bh1 = g_bhhp[dbase + 64 + i_], bh2 = g_bhhp[dbase + 128 + i_];
    size_t hb0 = ((size_t)dir*DM + m0)*DH + bb*64 + i_;
    #pragma unroll 4
    for (int idx = t; idx < 4096; idx += 256) {
        int ml = idx >> 6;
        int m = m0 + ml;
        int s = m & (DS - 1);
        int j = s + off;
        const float* pr = (j >= 0 && j < DS)
            ? g_proj + ((size_t)dir*DM + m + off)*DG + bb*192
            : g_ppad + dbase;
        float xr = pr[i_] + bi0;
        float xz = pr[64 + i_] + bi1;
        float xn = pr[128 + i_] + bi2;
        float hr = sC[ml*200 + i_] + bh0;
        float hz = sC[ml*200 + 64 + i_] + bh1;
        float hn = sC[ml*200 + 128 + i_] + bh2;
        float r  = sigf(xr + hr);
        float zz = sigf(xz + hz);
        float n  = tanhf(xn + r*hn);
        size_t hidx = hb0 + (size_t)ml*DH;
        float hold = g_h[hidx];
        float hv = (1.f - zz)*n + zz*hold;
        g_h[hidx] = hv;
        spl(hv, &g_hhi[wbuf][hidx], &g_hlo[wbuf][hidx]);
    }
}

// ---------- step 0 (h=0, no GEMM) ----------
__global__ void gru0(int offF, int offB) {
    int m = blockIdx.x, dir = blockIdx.y, hh = threadIdx.x;
    int off = dir ? offB : offF;
    int s = m & (DS - 1);
    int j = s + off;
    int bb = hh >> 6, i_ = hh & 63;
    int dbase = dir*DG + bb*192;
    const float* pr = (j >= 0 && j < DS)
        ? g_proj + ((size_t)dir*DM + m + off)*DG + bb*192
        : g_ppad + dbase;
    float xr = pr[i_] + g_bihp[dbase + i_];
    float xz = pr[64 + i_] + g_bihp[dbase + 64 + i_];
    float xn = pr[128 + i_] + g_bihp[dbase + 128 + i_];
    float hr = g_bhhp[dbase + i_];
    float hz = g_bhhp[dbase + 64 + i_];
    float hn = g_bhhp[dbase + 128 + i_];
    float r  = sigf(xr + hr);
    float zz = sigf(xz + hz);
    float n  = tanhf(xn + r*hn);
    float hv = (1.f - zz)*n;
    size_t hidx = ((size_t)dir*DM + m)*DH + hh;
    g_h[hidx] = hv;
    spl(hv, &g_hhi[0][hidx], &g_hlo[0][hidx]);
}

// ---------- tail ----------
__global__ void concat_stats(const int* x) {
    int blk = blockIdx.x, c = threadIdx.x;
    float s1 = 0, q1 = 0, s2 = 0, q2 = 0;
    for (int r = 0; r < 128; ++r) {
        int m = blk*128 + r;
        float mk = (x[m] > 0) ? 1.f : 0.f;
        float a = g_h[(size_t)m*DH + c] * mk;
        float b = g_h[((size_t)DM + m)*DH + c] * mk;
        g_hidden[(size_t)m*DC2 + c] = a;
        g_hidden[(size_t)m*DC2 + DH + c] = b;
        s1 += a; q1 += a*a; s2 += b; q2 += b*b;
    }
    g_bns[blk*DC2 + c] = s1;      g_bnq[blk*DC2 + c] = q1;
    g_bns[blk*DC2 + DH + c] = s2; g_bnq[blk*DC2 + DH + c] = q2;
}
__global__ void bn_fin(const float* gam, const float* bet) {
    int c = threadIdx.x;
    float s = 0, q = 0;
    for (int b = 0; b < 128; ++b) { s += g_bns[b*DC2 + c]; q += g_bnq[b*DC2 + c]; }
    float mu = s / (float)DM;
    float var = q / (float)DM - mu*mu;
    float sc = gam[c] * rsqrtf(var + 1e-5f);
    g_scale[c] = sc; g_shift[c] = bet[c] - mu*sc;
}
__global__ void norm_split(const int* x) {
    int m = blockIdx.x, c = threadIdx.x;
    float mk = (x[m] > 0) ? 1.f : 0.f;
    float v = (g_hidden[(size_t)m*DC2 + c] * g_scale[c] + g_shift[c]) * mk;
    spl(v, &g_nhi[(size_t)m*DC2 + c], &g_nlo[(size_t)m*DC2 + c]);
}
__global__ void poolk(const int* x, const float* mb) {
    int b = blockIdx.x, c = threadIdx.x;
    float bias = mb[c], mx = -3.4e38f;
    for (int s = 0; s < DS; ++s) {
        int m = b*DS + s;
        float v = (x[m] > 0) ? g_mlp[(size_t)m*DC2 + c] + bias : -65500.f;
        mx = fmaxf(mx, v);
    }
    g_pool[b*DC2 + c] = mx;
}
__global__ void headk(const float* lw, const float* lb, float* out) {
    int b = blockIdx.x, w = threadIdx.x >> 5, l = threadIdx.x & 31;
    float s = 0;
    for (int i = l; i < DC2; i += 32) s += g_pool[b*DC2 + i] * lw[(size_t)w*DC2 + i];
    #pragma unroll
    for (int o = 16; o; o >>= 1) s += __shfl_xor_sync(~0u, s, o);
    if (!l) out[b*2 + w] = s + lb[w];
}

extern "C" void kernel_launch(void* const* d_in, const int* in_sizes, int n_in,
                              void* d_out, int out_size) {
    const int*   x    = (const int*)d_in[0];
    const float* emb  = (const float*)d_in[5];
    const float* wihf = (const float*)d_in[6];
    const float* whhf = (const float*)d_in[7];
    const float* bihf = (const float*)d_in[8];
    const float* bhhf = (const float*)d_in[9];
    const float* wihb = (const float*)d_in[10];
    const float* whhb = (const float*)d_in[11];
    const float* bihb = (const float*)d_in[12];
    const float* bhhb = (const float*)d_in[13];
    const float* gam  = (const float*)d_in[14];
    const float* bet  = (const float*)d_in[15];
    const float* mw   = (const float*)d_in[16];
    const float* mb   = (const float*)d_in[17];
    const float* lw   = (const float*)d_in[18];
    const float* lb   = (const float*)d_in[19];
    float* out = (float*)d_out;

    cudaFuncSetAttribute(gemm3, cudaFuncAttributeMaxDynamicSharedMemorySize, 81920);
    cudaFuncSetAttribute(step_fused, cudaFuncAttributeMaxDynamicSharedMemorySize, 81920);

    prep_w<<<2*DG, DKE>>>(wihf, whhf, bihf, bhhf, wihb, whhb, bihb, bhhb);
    prep_mlp<<<DC2, DC2>>>(mw);
    pad_projk<<<(2*DG)/256, 256>>>(wihf, wihb, emb);
    gather_emb<<<DM, DKE>>>(x, emb);

    gemm3<<<dim3(DM/128, DG/128, 2), 256, 81920>>>(0);   // proj (packed, both dirs)
    gru0<<<dim3(DM, 2), DH>>>(-14, 14);
    for (int i = 1; i < 15; ++i)
        step_fused<<<dim3(DM/64, 4, 2), 256, 81920>>>((i + 1) & 1, i & 1, i - 14, 14 - i);

    concat_stats<<<128, 256>>>(x);
    bn_fin<<<1, DC2>>>(gam, bet);
    norm_split<<<DM, DC2>>>(x);
    gemm3<<<dim3(DM/128, DC2/128, 1), 256, 81920>>>(1);  // MLP
    poolk<<<32, DC2>>>(x, mb);
    headk<<<32, 64>>>(lw, lb, out);
}

// round 7
// speedup vs baseline: 1.9532x; 1.5864x over previous
#include <cuda_runtime.h>
#include <cuda_fp16.h>
#include <mma.h>
#include <cstdint>
using namespace nvcuda;

#define DM 16384
#define DS 512
#define DH 256
#define DG 768
#define DKE 320
#define DE 300
#define DC2 512

__device__ __align__(256) __half g_ehi[(size_t)DM*DKE], g_elo[(size_t)DM*DKE];
__device__ __align__(256) __half g_wih[2ull*DG*DKE];
__device__ __align__(256) __half g_whh[2ull*DG*DH];
__device__ __align__(256) __half g_mwh[(size_t)DC2*DC2], g_mwl[(size_t)DC2*DC2];
__device__ __align__(256) float g_proj[2ull*DM*DG];
__device__ __align__(256) float g_ppad[2*DG];
__device__ __align__(256) float g_hg[2ull*DM*DG];
__device__ __align__(256) float g_h[2ull*DM*DH];
__device__ __align__(256) __half g_hhi[2ull*DM*DH], g_hlo[2ull*DM*DH];
__device__ __align__(256) float g_hidden[(size_t)DM*DC2];
__device__ __align__(256) __half g_nhi[(size_t)DM*DC2], g_nlo[(size_t)DM*DC2];
__device__ __align__(256) float g_mlp[(size_t)DM*DC2];
__device__ __align__(256) float g_bns[128*DC2], g_bnq[128*DC2];
__device__ __align__(256) float g_scale[DC2], g_shift[DC2];
__device__ __align__(256) float g_pool[32*DC2];

__device__ __forceinline__ void cp16(void* s, const void* g) {
    unsigned a = (unsigned)__cvta_generic_to_shared(s);
    asm volatile("cp.async.cg.shared.global [%0], [%1], 16;\n" :: "r"(a), "l"(g));
}
__device__ __forceinline__ void spl(float v, __half* hi, __half* lo) {
    __half h = __float2half(v);
    *hi = h; *lo = __float2half(v - __half2float(h));
}
__device__ __forceinline__ float sigf(float x) { return 1.f / (1.f + __expf(-x)); }

// ---------- prep ----------
__global__ void prep_w(const float* wf, const float* hf, const float* wb, const float* hb) {
    int b = blockIdx.x; int dir = b / DG, g = b % DG; int k = threadIdx.x;
    const float* wi = dir ? wb : wf; const float* wh = dir ? hb : hf;
    float v = (k < DE) ? wi[(size_t)g*DE + k] : 0.f;
    g_wih[((size_t)dir*DG + g)*DKE + k] = __float2half(v);
    if (k < DH)
        g_whh[((size_t)dir*DG + g)*DH + k] = __float2half(wh[(size_t)g*DH + k]);
}
__global__ void prep_mlp(const float* mw) {
    size_t i = (size_t)blockIdx.x*DC2 + threadIdx.x;
    spl(mw[i], &g_mwh[i], &g_mwl[i]);
}
__global__ void pad_projk(const float* wf, const float* wb, const float* emb) {
    int idx = blockIdx.x*256 + threadIdx.x;
    int dir = idx / DG, g = idx % DG;
    const float* wi = dir ? wb : wf;
    float a = 0.f;
    for (int e = 0; e < DE; ++e) a += wi[(size_t)g*DE + e] * emb[e];
    g_ppad[idx] = a;
}
__global__ void gather_emb(const int* x, const float* emb) {
    int m = blockIdx.x, k = threadIdx.x;
    int tok = x[m];
    float v = (k < DE) ? emb[(size_t)tok*DE + k] : 0.f;
    spl(v, &g_ehi[(size_t)m*DKE + k], &g_elo[(size_t)m*DKE + k]);
}

// ---------- fp16 split GEMM: C = A @ B^T, tile 128x128, 256 thr ----------
// mode 0: proj (2-term)   mode 1: step hg (2-term)   mode 2: MLP (3-term)
__global__ void __launch_bounds__(256) gemm3(int mode) {
    extern __shared__ __half sm[];
    const int SA = 128*40;                 // elems per matrix per stage
    const int STG = 4*SA;                  // stage stride (4th slot used only in mode 2)
    const __half *Ah, *Al, *Bh, *Bl = nullptr; float* C; int K, N;
    int z = blockIdx.z;
    bool three = (mode == 2);
    if (mode == 0) { Ah = g_ehi; Al = g_elo;
        Bh = g_wih + (size_t)z*DG*DKE; C = g_proj + (size_t)z*DM*DG; K = DKE; N = DG; }
    else if (mode == 1) { Ah = g_hhi + (size_t)z*DM*DH; Al = g_hlo + (size_t)z*DM*DH;
        Bh = g_whh + (size_t)z*DG*DH; C = g_hg + (size_t)z*DM*DG; K = DH; N = DG; }
    else { Ah = g_nhi; Al = g_nlo; Bh = g_mwh; Bl = g_mwl; C = g_mlp; K = DC2; N = DC2; }
    int m0 = blockIdx.x*128, n0 = blockIdx.y*128, t = threadIdx.x;
    int NK = K >> 5;
    wmma::fragment<wmma::accumulator,16,16,16,float> acc[4][2];
    #pragma unroll
    for (int i = 0; i < 4; ++i)
        #pragma unroll
        for (int j = 0; j < 2; ++j) wmma::fill_fragment(acc[i][j], 0.f);
    auto load = [&](int kc, int st) {
        __half* b = sm + (size_t)st*STG;
        int k0 = kc*32;
        #pragma unroll
        for (int c = t; c < 512; c += 256) {
            int r = c >> 2, c8 = (c & 3)*8;
            cp16(b +        r*40 + c8, Ah + (size_t)(m0+r)*K + k0 + c8);
            cp16(b +   SA + r*40 + c8, Al + (size_t)(m0+r)*K + k0 + c8);
            cp16(b + 2*SA + r*40 + c8, Bh + (size_t)(n0+r)*K + k0 + c8);
            if (three)
                cp16(b + 3*SA + r*40 + c8, Bl + (size_t)(n0+r)*K + k0 + c8);
        }
        asm volatile("cp.async.commit_group;\n");
    };
    int w = t >> 5, wm = w & 1, wn = w >> 1;     // 2(m) x 4(n) warps
    load(0, 0);
    for (int kc = 0; kc < NK; ++kc) {
        int st = kc & 1;
        if (kc + 1 < NK) { load(kc+1, st^1); asm volatile("cp.async.wait_group 1;\n"); }
        else             { asm volatile("cp.async.wait_group 0;\n"); }
        __syncthreads();
        const __half *pA = sm + (size_t)st*STG, *pAl = pA + SA,
                     *pB = pA + 2*SA, *pBl = pA + 3*SA;
        #pragma unroll
        for (int kk = 0; kk < 32; kk += 16) {
            wmma::fragment<wmma::matrix_a,16,16,16,__half,wmma::row_major> fa[4], fal[4];
            wmma::fragment<wmma::matrix_b,16,16,16,__half,wmma::col_major> fb[2];
            #pragma unroll
            for (int i = 0; i < 4; ++i) {
                wmma::load_matrix_sync(fa[i],  pA  + (wm*64 + i*16)*40 + kk, 40);
                wmma::load_matrix_sync(fal[i], pAl + (wm*64 + i*16)*40 + kk, 40);
            }
            #pragma unroll
            for (int j = 0; j < 2; ++j)
                wmma::load_matrix_sync(fb[j], pB + (wn*32 + j*16)*40 + kk, 40);
            #pragma unroll
            for (int i = 0; i < 4; ++i)
                #pragma unroll
                for (int j = 0; j < 2; ++j) {
                    wmma::mma_sync(acc[i][j], fa[i],  fb[j], acc[i][j]);
                    wmma::mma_sync(acc[i][j], fal[i], fb[j], acc[i][j]);
                }
            if (three) {
                wmma::fragment<wmma::matrix_b,16,16,16,__half,wmma::col_major> fbl[2];
                #pragma unroll
                for (int j = 0; j < 2; ++j)
                    wmma::load_matrix_sync(fbl[j], pBl + (wn*32 + j*16)*40 + kk, 40);
                #pragma unroll
                for (int i = 0; i < 4; ++i)
                    #pragma unroll
                    for (int j = 0; j < 2; ++j)
                        wmma::mma_sync(acc[i][j], fa[i], fbl[j], acc[i][j]);
            }
        }
        __syncthreads();
    }
    #pragma unroll
    for (int i = 0; i < 4; ++i)
        #pragma unroll
        for (int j = 0; j < 2; ++j)
            wmma::store_matrix_sync(C + (size_t)(m0 + wm*64 + i*16)*N + n0 + wn*32 + j*16,
                                    acc[i][j], N, wmma::mem_row_major);
}

// ---------- GRU gate nonlinearity / state update ----------
__global__ void gru_update(const float* bihf, const float* bhhf,
                           const float* bihb, const float* bhhb,
                           int offF, int offB, int use_hg) {
    int m = blockIdx.x, dir = blockIdx.y, hh = threadIdx.x;
    int off = dir ? offB : offF;
    int s = m & (DS - 1);
    int j = s + off;
    const float* bih = dir ? bihb : bihf;
    const float* bhh = dir ? bhhb : bhhf;
    const float* pr = (j >= 0 && j < DS) ? g_proj + ((size_t)dir*DM + m + off)*DG
                                         : g_ppad + dir*DG;
    float xr = pr[hh] + bih[hh];
    float xz = pr[DH + hh] + bih[DH + hh];
    float xn = pr[2*DH + hh] + bih[2*DH + hh];
    float hr = bhh[hh], hz = bhh[DH + hh], hn = bhh[2*DH + hh], hold = 0.f;
    size_t hidx = ((size_t)dir*DM + m)*DH + hh;
    if (use_hg) {
        const float* hg = g_hg + ((size_t)dir*DM + m)*DG;
        hr += hg[hh]; hz += hg[DH + hh]; hn += hg[2*DH + hh];
        hold = g_h[hidx];
    }
    float r  = sigf(xr + hr);
    float zz = sigf(xz + hz);
    float n  = tanhf(xn + r*hn);
    float hv = (1.f - zz)*n + zz*hold;
    g_h[hidx] = hv;
    spl(hv, &g_hhi[hidx], &g_hlo[hidx]);
}

// ---------- tail ----------
__global__ void concat_stats(const int* x) {
    int blk = blockIdx.x, c = threadIdx.x;
    float s1 = 0, q1 = 0, s2 = 0, q2 = 0;
    for (int r = 0; r < 128; ++r) {
        int m = blk*128 + r;
        float mk = (x[m] > 0) ? 1.f : 0.f;
        float a = g_h[(size_t)m*DH + c] * mk;
        float b = g_h[((size_t)DM + m)*DH + c] * mk;
        g_hidden[(size_t)m*DC2 + c] = a;
        g_hidden[(size_t)m*DC2 + DH + c] = b;
        s1 += a; q1 += a*a; s2 += b; q2 += b*b;
    }
    g_bns[blk*DC2 + c] = s1;      g_bnq[blk*DC2 + c] = q1;
    g_bns[blk*DC2 + DH + c] = s2; g_bnq[blk*DC2 + DH + c] = q2;
}
__global__ void bn_fin(const float* gam, const float* bet) {
    int c = threadIdx.x;
    float s = 0, q = 0;
    for (int b = 0; b < 128; ++b) { s += g_bns[b*DC2 + c]; q += g_bnq[b*DC2 + c]; }
    float mu = s / (float)DM;
    float var = q / (float)DM - mu*mu;
    float sc = gam[c] * rsqrtf(var + 1e-5f);
    g_scale[c] = sc; g_shift[c] = bet[c] - mu*sc;
}
__global__ void norm_split(const int* x) {
    int m = blockIdx.x, c = threadIdx.x;
    float mk = (x[m] > 0) ? 1.f : 0.f;
    float v = (g_hidden[(size_t)m*DC2 + c] * g_scale[c] + g_shift[c]) * mk;
    spl(v, &g_nhi[(size_t)m*DC2 + c], &g_nlo[(size_t)m*DC2 + c]);
}
__global__ void poolk(const int* x, const float* mb) {
    int b = blockIdx.x, c = threadIdx.x;
    float bias = mb[c], mx = -3.4e38f;
    for (int s = 0; s < DS; ++s) {
        int m = b*DS + s;
        float v = (x[m] > 0) ? g_mlp[(size_t)m*DC2 + c] + bias : -65500.f;
        mx = fmaxf(mx, v);
    }
    g_pool[b*DC2 + c] = mx;
}
__global__ void headk(const float* lw, const float* lb, float* out) {
    int b = blockIdx.x, w = threadIdx.x >> 5, l = threadIdx.x & 31;
    float s = 0;
    for (int i = l; i < DC2; i += 32) s += g_pool[b*DC2 + i] * lw[(size_t)w*DC2 + i];
    #pragma unroll
    for (int o = 16; o; o >>= 1) s += __shfl_xor_sync(~0u, s, o);
    if (!l) out[b*2 + w] = s + lb[w];
}

extern "C" void kernel_launch(void* const* d_in, const int* in_sizes, int n_in,
                              void* d_out, int out_size) {
    const int*   x    = (const int*)d_in[0];
    const float* emb  = (const float*)d_in[5];
    const float* wihf = (const float*)d_in[6];
    const float* whhf = (const float*)d_in[7];
    const float* bihf = (const float*)d_in[8];
    const float* bhhf = (const float*)d_in[9];
    const float* wihb = (const float*)d_in[10];
    const float* whhb = (const float*)d_in[11];
    const float* bihb = (const float*)d_in[12];
    const float* bhhb = (const float*)d_in[13];
    const float* gam  = (const float*)d_in[14];
    const float* bet  = (const float*)d_in[15];
    const float* mw   = (const float*)d_in[16];
    const float* mb   = (const float*)d_in[17];
    const float* lw   = (const float*)d_in[18];
    const float* lb   = (const float*)d_in[19];
    float* out = (float*)d_out;

    cudaFuncSetAttribute(gemm3, cudaFuncAttributeMaxDynamicSharedMemorySize, 81920);

    prep_w<<<2*DG, DKE>>>(wihf, whhf, wihb, whhb);
    prep_mlp<<<DC2, DC2>>>(mw);
    pad_projk<<<(2*DG)/256, 256>>>(wihf, wihb, emb);
    gather_emb<<<DM, DKE>>>(x, emb);

    gemm3<<<dim3(DM/128, DG/128, 2), 256, 81920>>>(0);   // proj (both dirs, 2-term)
    gru_update<<<dim3(DM,2), DH>>>(bihf, bhhf, bihb, bhhb, -14, 14, 0);
    for (int i = 1; i < 15; ++i) {
        gemm3<<<dim3(DM/128, DG/128, 2), 256, 81920>>>(1);   // hg = h @ Whh^T (2-term)
        gru_update<<<dim3(DM,2), DH>>>(bihf, bhhf, bihb, bhhb, i - 14, 14 - i, 1);
    }
    concat_stats<<<128, 256>>>(x);
    bn_fin<<<1, DC2>>>(gam, bet);
    norm_split<<<DM, DC2>>>(x);
    gemm3<<<dim3(DM/128, DC2/128, 1), 256, 81920>>>(2);  // MLP (3-term)
    poolk<<<32, DC2>>>(x, mb);
    headk<<<32, 64>>>(lw, lb, out);
}

// round 9
// speedup vs baseline: 2.0065x; 1.0273x over previous
#include <cuda_runtime.h>
#include <cuda_fp16.h>
#include <mma.h>
#include <cstdint>
using namespace nvcuda;

#define DM 16384
#define DS 512
#define DH 256
#define DG 768
#define DKE 320
#define DE 300
#define DC2 512

__device__ __align__(256) __half g_ehi[(size_t)DM*DKE], g_elo[(size_t)DM*DKE];
__device__ __align__(256) __half g_wih[2ull*DG*DKE];
__device__ __align__(256) __half g_whh[2ull*DG*DH];
__device__ __align__(256) __half g_mwh[(size_t)DC2*DC2], g_mwl[(size_t)DC2*DC2];
__device__ __align__(256) __half g_proj[2ull*DM*DG];     // fp16, bih folded in
__device__ __align__(256) __half g_ppad[2*DG];           // fp16, bih folded in
__device__ __align__(256) __half g_hg[2ull*DM*DG];       // fp16, bhh folded in
__device__ __align__(256) float g_bih[2*DG], g_bhh[2*DG];
__device__ __align__(256) __half g_hhi[2ull*DM*DH], g_hlo[2ull*DM*DH];
__device__ __align__(256) float g_hidden[(size_t)DM*DC2];
__device__ __align__(256) __half g_nhi[(size_t)DM*DC2], g_nlo[(size_t)DM*DC2];
__device__ __align__(256) float g_mlp[(size_t)DM*DC2];
__device__ __align__(256) float g_bns[128*DC2], g_bnq[128*DC2];
__device__ __align__(256) float g_scale[DC2], g_shift[DC2];
__device__ __align__(256) float g_pool[32*DC2];

__device__ __forceinline__ void cp16(void* s, const void* g) {
    unsigned a = (unsigned)__cvta_generic_to_shared(s);
    asm volatile("cp.async.cg.shared.global [%0], [%1], 16;\n" :: "r"(a), "l"(g));
}
__device__ __forceinline__ void spl(float v, __half* hi, __half* lo) {
    __half h = __float2half(v);
    *hi = h; *lo = __float2half(v - __half2float(h));
}
__device__ __forceinline__ float sigf(float x) { return 1.f / (1.f + __expf(-x)); }

// ---------- prep ----------
__global__ void prep_w(const float* wf, const float* hf, const float* wb, const float* hb) {
    int b = blockIdx.x; int dir = b / DG, g = b % DG; int k = threadIdx.x;
    const float* wi = dir ? wb : wf; const float* wh = dir ? hb : hf;
    float v = (k < DE) ? wi[(size_t)g*DE + k] : 0.f;
    g_wih[((size_t)dir*DG + g)*DKE + k] = __float2half(v);
    if (k < DH)
        g_whh[((size_t)dir*DG + g)*DH + k] = __float2half(wh[(size_t)g*DH + k]);
}
__global__ void prep_bias(const float* bif, const float* bib,
                          const float* bhf, const float* bhb) {
    int i = blockIdx.x*256 + threadIdx.x;     // 0..1535
    if (i < DG) { g_bih[i] = bif[i]; g_bhh[i] = bhf[i]; }
    else        { g_bih[i] = bib[i-DG]; g_bhh[i] = bhb[i-DG]; }
}
__global__ void prep_mlp(const float* mw) {
    size_t i = (size_t)blockIdx.x*DC2 + threadIdx.x;
    spl(mw[i], &g_mwh[i], &g_mwl[i]);
}
__global__ void pad_projk(const float* wf, const float* wb, const float* emb) {
    int idx = blockIdx.x*256 + threadIdx.x;
    int dir = idx / DG, g = idx % DG;
    const float* wi = dir ? wb : wf;
    float a = 0.f;
    for (int e = 0; e < DE; ++e) a += wi[(size_t)g*DE + e] * emb[e];
    g_ppad[idx] = __float2half(a + g_bih[idx]);
}
__global__ void gather_emb(const int* x, const float* emb) {
    int m = blockIdx.x, k = threadIdx.x;
    int tok = x[m];
    float v = (k < DE) ? emb[(size_t)tok*DE + k] : 0.f;
    spl(v, &g_ehi[(size_t)m*DKE + k], &g_elo[(size_t)m*DKE + k]);
}

// ---------- fp16 split GEMM: C = A @ B^T, tile 128x128, 256 thr ----------
// mode 0: proj (2-term, fp16 out + bih)  mode 1: hg (2-term, fp16 out + bhh)
// mode 2: MLP (3-term, fp32 out)
__global__ void __launch_bounds__(256) gemm3(int mode) {
    extern __shared__ __half sm[];
    const int SA = 128*40;
    const int STG = 4*SA;
    const __half *Ah, *Al, *Bh, *Bl = nullptr; int K, N;
    __half* Ch = nullptr; float* Cf = nullptr; const float* bias = nullptr;
    int z = blockIdx.z;
    bool three = (mode == 2);
    if (mode == 0) { Ah = g_ehi; Al = g_elo;
        Bh = g_wih + (size_t)z*DG*DKE; Ch = g_proj + (size_t)z*DM*DG;
        bias = g_bih + z*DG; K = DKE; N = DG; }
    else if (mode == 1) { Ah = g_hhi + (size_t)z*DM*DH; Al = g_hlo + (size_t)z*DM*DH;
        Bh = g_whh + (size_t)z*DG*DH; Ch = g_hg + (size_t)z*DM*DG;
        bias = g_bhh + z*DG; K = DH; N = DG; }
    else { Ah = g_nhi; Al = g_nlo; Bh = g_mwh; Bl = g_mwl; Cf = g_mlp; K = DC2; N = DC2; }
    int m0 = blockIdx.x*128, n0 = blockIdx.y*128, t = threadIdx.x;
    int NK = K >> 5;
    wmma::fragment<wmma::accumulator,16,16,16,float> acc[4][2];
    #pragma unroll
    for (int i = 0; i < 4; ++i)
        #pragma unroll
        for (int j = 0; j < 2; ++j) wmma::fill_fragment(acc[i][j], 0.f);
    auto load = [&](int kc, int st) {
        __half* b = sm + (size_t)st*STG;
        int k0 = kc*32;
        #pragma unroll
        for (int c = t; c < 512; c += 256) {
            int r = c >> 2, c8 = (c & 3)*8;
            cp16(b +        r*40 + c8, Ah + (size_t)(m0+r)*K + k0 + c8);
            cp16(b +   SA + r*40 + c8, Al + (size_t)(m0+r)*K + k0 + c8);
            cp16(b + 2*SA + r*40 + c8, Bh + (size_t)(n0+r)*K + k0 + c8);
            if (three)
                cp16(b + 3*SA + r*40 + c8, Bl + (size_t)(n0+r)*K + k0 + c8);
        }
        asm volatile("cp.async.commit_group;\n");
    };
    int w = t >> 5, wm = w & 1, wn = w >> 1;
    load(0, 0);
    for (int kc = 0; kc < NK; ++kc) {
        int st = kc & 1;
        if (kc + 1 < NK) { load(kc+1, st^1); asm volatile("cp.async.wait_group 1;\n"); }
        else             { asm volatile("cp.async.wait_group 0;\n"); }
        __syncthreads();
        const __half *pA = sm + (size_t)st*STG, *pAl = pA + SA,
                     *pB = pA + 2*SA, *pBl = pA + 3*SA;
        #pragma unroll
        for (int kk = 0; kk < 32; kk += 16) {
            wmma::fragment<wmma::matrix_a,16,16,16,__half,wmma::row_major> fa[4], fal[4];
            wmma::fragment<wmma::matrix_b,16,16,16,__half,wmma::col_major> fb[2];
            #pragma unroll
            for (int i = 0; i < 4; ++i) {
                wmma::load_matrix_sync(fa[i],  pA  + (wm*64 + i*16)*40 + kk, 40);
                wmma::load_matrix_sync(fal[i], pAl + (wm*64 + i*16)*40 + kk, 40);
            }
            #pragma unroll
            for (int j = 0; j < 2; ++j)
                wmma::load_matrix_sync(fb[j], pB + (wn*32 + j*16)*40 + kk, 40);
            #pragma unroll
            for (int i = 0; i < 4; ++i)
                #pragma unroll
                for (int j = 0; j < 2; ++j) {
                    wmma::mma_sync(acc[i][j], fa[i],  fb[j], acc[i][j]);
                    wmma::mma_sync(acc[i][j], fal[i], fb[j], acc[i][j]);
                }
            if (three) {
                wmma::fragment<wmma::matrix_b,16,16,16,__half,wmma::col_major> fbl[2];
                #pragma unroll
                for (int j = 0; j < 2; ++j)
                    wmma::load_matrix_sync(fbl[j], pBl + (wn*32 + j*16)*40 + kk, 40);
                #pragma unroll
                for (int i = 0; i < 4; ++i)
                    #pragma unroll
                    for (int j = 0; j < 2; ++j)
                        wmma::mma_sync(acc[i][j], fa[i], fbl[j], acc[i][j]);
            }
        }
        __syncthreads();
    }
    if (three) {
        #pragma unroll
        for (int i = 0; i < 4; ++i)
            #pragma unroll
            for (int j = 0; j < 2; ++j)
                wmma::store_matrix_sync(Cf + (size_t)(m0 + wm*64 + i*16)*N + n0 + wn*32 + j*16,
                                        acc[i][j], N, wmma::mem_row_major);
    } else {
        // stage through smem, add bias, write fp16 (uint4 = 8 halves per store)
        float* sC = (float*)sm;                      // 128 x 132
        #pragma unroll
        for (int i = 0; i < 4; ++i)
            #pragma unroll
            for (int j = 0; j < 2; ++j)
                wmma::store_matrix_sync(sC + (wm*64 + i*16)*132 + wn*32 + j*16,
                                        acc[i][j], 132, wmma::mem_row_major);
        __syncthreads();
        int r = t >> 1, c0 = (t & 1)*64;
        #pragma unroll
        for (int j = 0; j < 64; j += 8) {
            __half tmp[8];
            #pragma unroll
            for (int k = 0; k < 8; ++k)
                tmp[k] = __float2half(sC[r*132 + c0 + j + k] + bias[n0 + c0 + j + k]);
            *(uint4*)(Ch + (size_t)(m0 + r)*N + n0 + c0 + j) = *(uint4*)tmp;
        }
    }
}

// ---------- GRU gate nonlinearity / state update (half2, 128 thr x 2 ch) ----------
__global__ void gru_update(int offF, int offB, int use_hg) {
    int m = blockIdx.x, dir = blockIdx.y, c = threadIdx.x;    // c: 0..127 (2 channels)
    int off = dir ? offB : offF;
    int j = (m & (DS - 1)) + off;
    const __half* pr = (j >= 0 && j < DS) ? g_proj + ((size_t)dir*DM + m + off)*DG
                                          : g_ppad + dir*DG;
    float2 xr = __half22float2(*(const half2*)(pr + 2*c));
    float2 xz = __half22float2(*(const half2*)(pr + DH + 2*c));
    float2 xn = __half22float2(*(const half2*)(pr + 2*DH + 2*c));
    float2 hr, hz, hn;
    float2 hold = make_float2(0.f, 0.f);
    size_t hidx = ((size_t)dir*DM + m)*DH + 2*c;
    if (use_hg) {
        const __half* hg = g_hg + ((size_t)dir*DM + m)*DG;
        hr = __half22float2(*(const half2*)(hg + 2*c));
        hz = __half22float2(*(const half2*)(hg + DH + 2*c));
        hn = __half22float2(*(const half2*)(hg + 2*DH + 2*c));
        float2 hi = __half22float2(*(const half2*)(g_hhi + hidx));
        float2 lo = __half22float2(*(const half2*)(g_hlo + hidx));
        hold = make_float2(hi.x + lo.x, hi.y + lo.y);
    } else {
        int db = dir*DG + 2*c;
        hr = make_float2(g_bhh[db],        g_bhh[db+1]);
        hz = make_float2(g_bhh[DH+db],     g_bhh[DH+db+1]);
        hn = make_float2(g_bhh[2*DH+db],   g_bhh[2*DH+db+1]);
    }
    float r0 = sigf(xr.x + hr.x), r1 = sigf(xr.y + hr.y);
    float z0 = sigf(xz.x + hz.x), z1 = sigf(xz.y + hz.y);
    float n0 = tanhf(xn.x + r0*hn.x), n1 = tanhf(xn.y + r1*hn.y);
    float h0 = (1.f - z0)*n0 + z0*hold.x;
    float h1 = (1.f - z1)*n1 + z1*hold.y;
    __half hi0, lo0, hi1, lo1;
    spl(h0, &hi0, &lo0); spl(h1, &hi1, &lo1);
    *(half2*)(g_hhi + hidx) = __halves2half2(hi0, hi1);
    *(half2*)(g_hlo + hidx) = __halves2half2(lo0, lo1);
}

// ---------- tail ----------
__global__ void concat_stats(const int* x) {
    int blk = blockIdx.x, c = threadIdx.x;
    float s1 = 0, q1 = 0, s2 = 0, q2 = 0;
    for (int r = 0; r < 128; ++r) {
        int m = blk*128 + r;
        float mk = (x[m] > 0) ? 1.f : 0.f;
        size_t i1 = (size_t)m*DH + c, i2 = ((size_t)DM + m)*DH + c;
        float a = (__half2float(g_hhi[i1]) + __half2float(g_hlo[i1])) * mk;
        float b = (__half2float(g_hhi[i2]) + __half2float(g_hlo[i2])) * mk;
        g_hidden[(size_t)m*DC2 + c] = a;
        g_hidden[(size_t)m*DC2 + DH + c] = b;
        s1 += a; q1 += a*a; s2 += b; q2 += b*b;
    }
    g_bns[blk*DC2 + c] = s1;      g_bnq[blk*DC2 + c] = q1;
    g_bns[blk*DC2 + DH + c] = s2; g_bnq[blk*DC2 + DH + c] = q2;
}
__global__ void bn_fin(const float* gam, const float* bet) {
    int c = threadIdx.x;
    float s = 0, q = 0;
    for (int b = 0; b < 128; ++b) { s += g_bns[b*DC2 + c]; q += g_bnq[b*DC2 + c]; }
    float mu = s / (float)DM;
    float var = q / (float)DM - mu*mu;
    float sc = gam[c] * rsqrtf(var + 1e-5f);
    g_scale[c] = sc; g_shift[c] = bet[c] - mu*sc;
}
__global__ void norm_split(const int* x) {
    int m = blockIdx.x, c = threadIdx.x;
    float mk = (x[m] > 0) ? 1.f : 0.f;
    float v = (g_hidden[(size_t)m*DC2 + c] * g_scale[c] + g_shift[c]) * mk;
    spl(v, &g_nhi[(size_t)m*DC2 + c], &g_nlo[(size_t)m*DC2 + c]);
}
__global__ void poolk(const int* x, const float* mb) {
    int b = blockIdx.x, c = threadIdx.x;
    float bias = mb[c], mx = -3.4e38f;
    for (int s = 0; s < DS; ++s) {
        int m = b*DS + s;
        float v = (x[m] > 0) ? g_mlp[(size_t)m*DC2 + c] + bias : -65500.f;
        mx = fmaxf(mx, v);
    }
    g_pool[b*DC2 + c] = mx;
}
__global__ void headk(const float* lw, const float* lb, float* out) {
    int b = blockIdx.x, w = threadIdx.x >> 5, l = threadIdx.x & 31;
    float s = 0;
    for (int i = l; i < DC2; i += 32) s += g_pool[b*DC2 + i] * lw[(size_t)w*DC2 + i];
    #pragma unroll
    for (int o = 16; o; o >>= 1) s += __shfl_xor_sync(~0u, s, o);
    if (!l) out[b*2 + w] = s + lb[w];
}

extern "C" void kernel_launch(void* const* d_in, const int* in_sizes, int n_in,
                              void* d_out, int out_size) {
    const int*   x    = (const int*)d_in[0];
    const float* emb  = (const float*)d_in[5];
    const float* wihf = (const float*)d_in[6];
    const float* whhf = (const float*)d_in[7];
    const float* bihf = (const float*)d_in[8];
    const float* bhhf = (const float*)d_in[9];
    const float* wihb = (const float*)d_in[10];
    const float* whhb = (const float*)d_in[11];
    const float* bihb = (const float*)d_in[12];
    const float* bhhb = (const float*)d_in[13];
    const float* gam  = (const float*)d_in[14];
    const float* bet  = (const float*)d_in[15];
    const float* mw   = (const float*)d_in[16];
    const float* mb   = (const float*)d_in[17];
    const float* lw   = (const float*)d_in[18];
    const float* lb   = (const float*)d_in[19];
    float* out = (float*)d_out;

    cudaFuncSetAttribute(gemm3, cudaFuncAttributeMaxDynamicSharedMemorySize, 81920);

    prep_w<<<2*DG, DKE>>>(wihf, whhf, wihb, whhb);
    prep_bias<<<6, 256>>>(bihf, bihb, bhhf, bhhb);
    prep_mlp<<<DC2, DC2>>>(mw);
    pad_projk<<<(2*DG)/256, 256>>>(wihf, wihb, emb);
    gather_emb<<<DM, DKE>>>(x, emb);

    gemm3<<<dim3(DM/128, DG/128, 2), 256, 81920>>>(0);   // proj fp16 (+bih)
    gru_update<<<dim3(DM,2), 128>>>(-14, 14, 0);
    for (int i = 1; i < 15; ++i) {
        gemm3<<<dim3(DM/128, DG/128, 2), 256, 81920>>>(1);   // hg fp16 (+bhh)
        gru_update<<<dim3(DM,2), 128>>>(i - 14, 14 - i, 1);
    }
    concat_stats<<<128, 256>>>(x);
    bn_fin<<<1, DC2>>>(gam, bet);
    norm_split<<<DM, DC2>>>(x);
    gemm3<<<dim3(DM/128, DC2/128, 1), 256, 81920>>>(2);  // MLP fp32
    poolk<<<32, DC2>>>(x, mb);
    headk<<<32, 64>>>(lw, lb, out);
}

// round 10
// speedup vs baseline: 2.1159x; 1.0545x over previous
#include <cuda_runtime.h>
#include <cuda_fp16.h>
#include <mma.h>
#include <cstdint>
using namespace nvcuda;

#define DM 16384
#define DS 512
#define DH 256
#define DG 768
#define DKE 320
#define DE 300
#define DC2 512

__device__ __align__(256) __half g_ehi[(size_t)DM*DKE];
__device__ __align__(256) __half g_wih[2ull*DG*DKE];
__device__ __align__(256) __half g_whh[2ull*DG*DH];
__device__ __align__(256) __half g_mwh[(size_t)DC2*DC2], g_mwl[(size_t)DC2*DC2];
__device__ __align__(256) __half g_proj[2ull*DM*DG];     // fp16, bih folded in
__device__ __align__(256) __half g_ppad[2*DG];           // fp16, bih folded in
__device__ __align__(256) __half g_hg[2ull*DM*DG];       // fp16, bhh folded in
__device__ __align__(256) float g_bih[2*DG], g_bhh[2*DG];
__device__ __align__(256) __half g_hhi[2ull*DM*DH], g_hlo[2ull*DM*DH];
__device__ __align__(256) float g_hidden[(size_t)DM*DC2];
__device__ __align__(256) __half g_nhi[(size_t)DM*DC2], g_nlo[(size_t)DM*DC2];
__device__ __align__(256) float g_mlp[(size_t)DM*DC2];
__device__ __align__(256) float g_bns[128*DC2], g_bnq[128*DC2];
__device__ __align__(256) float g_scale[DC2], g_shift[DC2];
__device__ __align__(256) float g_pool[32*DC2];

__device__ __forceinline__ void cp16(void* s, const void* g) {
    unsigned a = (unsigned)__cvta_generic_to_shared(s);
    asm volatile("cp.async.cg.shared.global [%0], [%1], 16;\n" :: "r"(a), "l"(g));
}
__device__ __forceinline__ void spl(float v, __half* hi, __half* lo) {
    __half h = __float2half(v);
    *hi = h; *lo = __float2half(v - __half2float(h));
}
__device__ __forceinline__ float sigf(float x) { return 1.f / (1.f + __expf(-x)); }

// ---------- prep ----------
__global__ void prep_w(const float* wf, const float* hf, const float* wb, const float* hb) {
    int b = blockIdx.x; int dir = b / DG, g = b % DG; int k = threadIdx.x;
    const float* wi = dir ? wb : wf; const float* wh = dir ? hb : hf;
    float v = (k < DE) ? wi[(size_t)g*DE + k] : 0.f;
    g_wih[((size_t)dir*DG + g)*DKE + k] = __float2half(v);
    if (k < DH)
        g_whh[((size_t)dir*DG + g)*DH + k] = __float2half(wh[(size_t)g*DH + k]);
}
__global__ void prep_bias(const float* bif, const float* bib,
                          const float* bhf, const float* bhb) {
    int i = blockIdx.x*256 + threadIdx.x;     // 0..1535
    if (i < DG) { g_bih[i] = bif[i]; g_bhh[i] = bhf[i]; }
    else        { g_bih[i] = bib[i-DG]; g_bhh[i] = bhb[i-DG]; }
}
__global__ void prep_mlp(const float* mw) {
    size_t i = (size_t)blockIdx.x*DC2 + threadIdx.x;
    spl(mw[i], &g_mwh[i], &g_mwl[i]);
}
__global__ void pad_projk(const float* wf, const float* wb, const float* emb) {
    int idx = blockIdx.x;                      // 0..1535
    int dir = idx / DG, g = idx % DG;
    const float* wi = dir ? wb : wf;
    float a = 0.f;
    for (int e = threadIdx.x; e < DE; e += 128) a += wi[(size_t)g*DE + e] * emb[e];
    __shared__ float red[4];
    #pragma unroll
    for (int o = 16; o; o >>= 1) a += __shfl_xor_sync(~0u, a, o);
    if ((threadIdx.x & 31) == 0) red[threadIdx.x >> 5] = a;
    __syncthreads();
    if (threadIdx.x == 0)
        g_ppad[idx] = __float2half(red[0] + red[1] + red[2] + red[3] + g_bih[idx]);
}
__global__ void gather_emb(const int* x, const float* emb) {
    int m = blockIdx.x, k = threadIdx.x;
    int tok = x[m];
    g_ehi[(size_t)m*DKE + k] = __float2half((k < DE) ? emb[(size_t)tok*DE + k] : 0.f);
}

// ---------- fp16 GEMM: C = A @ B^T, tile 128x128, 256 thr ----------
// mode 0: proj (1-term, fp16 out + bih)  mode 1: hg (1-term, fp16 out + bhh)
// mode 2: MLP (3-term, fp32 out)
__global__ void __launch_bounds__(256) gemm3(int mode) {
    extern __shared__ __half sm[];
    const int SA = 128*40;
    const int STG = 4*SA;
    const __half *Ah, *Al = nullptr, *Bh, *Bl = nullptr; int K, N;
    __half* Ch = nullptr; float* Cf = nullptr; const float* bias = nullptr;
    int z = blockIdx.z;
    bool three = (mode == 2);
    if (mode == 0) { Ah = g_ehi;
        Bh = g_wih + (size_t)z*DG*DKE; Ch = g_proj + (size_t)z*DM*DG;
        bias = g_bih + z*DG; K = DKE; N = DG; }
    else if (mode == 1) { Ah = g_hhi + (size_t)z*DM*DH;
        Bh = g_whh + (size_t)z*DG*DH; Ch = g_hg + (size_t)z*DM*DG;
        bias = g_bhh + z*DG; K = DH; N = DG; }
    else { Ah = g_nhi; Al = g_nlo; Bh = g_mwh; Bl = g_mwl; Cf = g_mlp; K = DC2; N = DC2; }
    int m0 = blockIdx.x*128, n0 = blockIdx.y*128, t = threadIdx.x;
    int NK = K >> 5;
    wmma::fragment<wmma::accumulator,16,16,16,float> acc[4][2];
    #pragma unroll
    for (int i = 0; i < 4; ++i)
        #pragma unroll
        for (int j = 0; j < 2; ++j) wmma::fill_fragment(acc[i][j], 0.f);
    auto load = [&](int kc, int st) {
        __half* b = sm + (size_t)st*STG;
        int k0 = kc*32;
        #pragma unroll
        for (int c = t; c < 512; c += 256) {
            int r = c >> 2, c8 = (c & 3)*8;
            cp16(b +        r*40 + c8, Ah + (size_t)(m0+r)*K + k0 + c8);
            cp16(b + 2*SA + r*40 + c8, Bh + (size_t)(n0+r)*K + k0 + c8);
            if (three) {
                cp16(b +   SA + r*40 + c8, Al + (size_t)(m0+r)*K + k0 + c8);
                cp16(b + 3*SA + r*40 + c8, Bl + (size_t)(n0+r)*K + k0 + c8);
            }
        }
        asm volatile("cp.async.commit_group;\n");
    };
    int w = t >> 5, wm = w & 1, wn = w >> 1;
    load(0, 0);
    for (int kc = 0; kc < NK; ++kc) {
        int st = kc & 1;
        if (kc + 1 < NK) { load(kc+1, st^1); asm volatile("cp.async.wait_group 1;\n"); }
        else             { asm volatile("cp.async.wait_group 0;\n"); }
        __syncthreads();
        const __half *pA = sm + (size_t)st*STG, *pAl = pA + SA,
                     *pB = pA + 2*SA, *pBl = pA + 3*SA;
        #pragma unroll
        for (int kk = 0; kk < 32; kk += 16) {
            wmma::fragment<wmma::matrix_a,16,16,16,__half,wmma::row_major> fa[4];
            wmma::fragment<wmma::matrix_b,16,16,16,__half,wmma::col_major> fb[2];
            #pragma unroll
            for (int i = 0; i < 4; ++i)
                wmma::load_matrix_sync(fa[i], pA + (wm*64 + i*16)*40 + kk, 40);
            #pragma unroll
            for (int j = 0; j < 2; ++j)
                wmma::load_matrix_sync(fb[j], pB + (wn*32 + j*16)*40 + kk, 40);
            #pragma unroll
            for (int i = 0; i < 4; ++i)
                #pragma unroll
                for (int j = 0; j < 2; ++j)
                    wmma::mma_sync(acc[i][j], fa[i], fb[j], acc[i][j]);
            if (three) {
                wmma::fragment<wmma::matrix_a,16,16,16,__half,wmma::row_major> fal[4];
                wmma::fragment<wmma::matrix_b,16,16,16,__half,wmma::col_major> fbl[2];
                #pragma unroll
                for (int i = 0; i < 4; ++i)
                    wmma::load_matrix_sync(fal[i], pAl + (wm*64 + i*16)*40 + kk, 40);
                #pragma unroll
                for (int j = 0; j < 2; ++j)
                    wmma::load_matrix_sync(fbl[j], pBl + (wn*32 + j*16)*40 + kk, 40);
                #pragma unroll
                for (int i = 0; i < 4; ++i)
                    #pragma unroll
                    for (int j = 0; j < 2; ++j) {
                        wmma::mma_sync(acc[i][j], fal[i], fb[j],  acc[i][j]);
                        wmma::mma_sync(acc[i][j], fa[i],  fbl[j], acc[i][j]);
                    }
            }
        }
        __syncthreads();
    }
    if (three) {
        #pragma unroll
        for (int i = 0; i < 4; ++i)
            #pragma unroll
            for (int j = 0; j < 2; ++j)
                wmma::store_matrix_sync(Cf + (size_t)(m0 + wm*64 + i*16)*N + n0 + wn*32 + j*16,
                                        acc[i][j], N, wmma::mem_row_major);
    } else {
        // stage through smem, add bias, write fp16 (uint4 = 8 halves)
        float* sC = (float*)sm;                      // 128 x 132
        #pragma unroll
        for (int i = 0; i < 4; ++i)
            #pragma unroll
            for (int j = 0; j < 2; ++j)
                wmma::store_matrix_sync(sC + (wm*64 + i*16)*132 + wn*32 + j*16,
                                        acc[i][j], 132, wmma::mem_row_major);
        __syncthreads();
        int r = t >> 1, c0 = (t & 1)*64;
        #pragma unroll
        for (int j = 0; j < 64; j += 8) {
            __half tmp[8];
            #pragma unroll
            for (int k = 0; k < 8; ++k)
                tmp[k] = __float2half(sC[r*132 + c0 + j + k] + bias[n0 + c0 + j + k]);
            *(uint4*)(Ch + (size_t)(m0 + r)*N + n0 + c0 + j) = *(uint4*)tmp;
        }
    }
}

// ---------- GRU gate nonlinearity / state update (half2, 128 thr x 2 ch) ----------
__global__ void gru_update(int offF, int offB, int use_hg) {
    int m = blockIdx.x, dir = blockIdx.y, c = threadIdx.x;
    int off = dir ? offB : offF;
    int j = (m & (DS - 1)) + off;
    const __half* pr = (j >= 0 && j < DS) ? g_proj + ((size_t)dir*DM + m + off)*DG
                                          : g_ppad + dir*DG;
    float2 xr = __half22float2(*(const half2*)(pr + 2*c));
    float2 xz = __half22float2(*(const half2*)(pr + DH + 2*c));
    float2 xn = __half22float2(*(const half2*)(pr + 2*DH + 2*c));
    float2 hr, hz, hn;
    float2 hold = make_float2(0.f, 0.f);
    size_t hidx = ((size_t)dir*DM + m)*DH + 2*c;
    if (use_hg) {
        const __half* hg = g_hg + ((size_t)dir*DM + m)*DG;
        hr = __half22float2(*(const half2*)(hg + 2*c));
        hz = __half22float2(*(const half2*)(hg + DH + 2*c));
        hn = __half22float2(*(const half2*)(hg + 2*DH + 2*c));
        float2 hi = __half22float2(*(const half2*)(g_hhi + hidx));
        float2 lo = __half22float2(*(const half2*)(g_hlo + hidx));
        hold = make_float2(hi.x + lo.x, hi.y + lo.y);
    } else {
        int db = dir*DG + 2*c;
        hr = make_float2(g_bhh[db],        g_bhh[db+1]);
        hz = make_float2(g_bhh[DH+db],     g_bhh[DH+db+1]);
        hn = make_float2(g_bhh[2*DH+db],   g_bhh[2*DH+db+1]);
    }
    float r0 = sigf(xr.x + hr.x), r1 = sigf(xr.y + hr.y);
    float z0 = sigf(xz.x + hz.x), z1 = sigf(xz.y + hz.y);
    float n0 = tanhf(xn.x + r0*hn.x), n1 = tanhf(xn.y + r1*hn.y);
    float h0 = (1.f - z0)*n0 + z0*hold.x;
    float h1 = (1.f - z1)*n1 + z1*hold.y;
    __half hi0, lo0, hi1, lo1;
    spl(h0, &hi0, &lo0); spl(h1, &hi1, &lo1);
    *(half2*)(g_hhi + hidx) = __halves2half2(hi0, hi1);
    *(half2*)(g_hlo + hidx) = __halves2half2(lo0, lo1);
}

// ---------- tail ----------
__global__ void concat_stats(const int* x) {
    int blk = blockIdx.x, c = threadIdx.x;
    float s1 = 0, q1 = 0, s2 = 0, q2 = 0;
    for (int r = 0; r < 128; ++r) {
        int m = blk*128 + r;
        float mk = (x[m] > 0) ? 1.f : 0.f;
        size_t i1 = (size_t)m*DH + c, i2 = ((size_t)DM + m)*DH + c;
        float a = (__half2float(g_hhi[i1]) + __half2float(g_hlo[i1])) * mk;
        float b = (__half2float(g_hhi[i2]) + __half2float(g_hlo[i2])) * mk;
        g_hidden[(size_t)m*DC2 + c] = a;
        g_hidden[(size_t)m*DC2 + DH + c] = b;
        s1 += a; q1 += a*a; s2 += b; q2 += b*b;
    }
    g_bns[blk*DC2 + c] = s1;      g_bnq[blk*DC2 + c] = q1;
    g_bns[blk*DC2 + DH + c] = s2; g_bnq[blk*DC2 + DH + c] = q2;
}
__global__ void bn_fin(const float* gam, const float* bet) {
    int c = threadIdx.x;
    float s = 0, q = 0;
    for (int b = 0; b < 128; ++b) { s += g_bns[b*DC2 + c]; q += g_bnq[b*DC2 + c]; }
    float mu = s / (float)DM;
    float var = q / (float)DM - mu*mu;
    float sc = gam[c] * rsqrtf(var + 1e-5f);
    g_scale[c] = sc; g_shift[c] = bet[c] - mu*sc;
}
__global__ void norm_split(const int* x) {
    int m = blockIdx.x, c = threadIdx.x;
    float mk = (x[m] > 0) ? 1.f : 0.f;
    float v = (g_hidden[(size_t)m*DC2 + c] * g_scale[c] + g_shift[c]) * mk;
    spl(v, &g_nhi[(size_t)m*DC2 + c], &g_nlo[(size_t)m*DC2 + c]);
}
__global__ void poolk(const int* x, const float* mb) {
    int b = blockIdx.x, c = threadIdx.x;
    float bias = mb[c], mx = -3.4e38f;
    for (int s = 0; s < DS; ++s) {
        int m = b*DS + s;
        float v = (x[m] > 0) ? g_mlp[(size_t)m*DC2 + c] + bias : -65500.f;
        mx = fmaxf(mx, v);
    }
    g_pool[b*DC2 + c] = mx;
}
__global__ void headk(const float* lw, const float* lb, float* out) {
    int b = blockIdx.x, w = threadIdx.x >> 5, l = threadIdx.x & 31;
    float s = 0;
    for (int i = l; i < DC2; i += 32) s += g_pool[b*DC2 + i] * lw[(size_t)w*DC2 + i];
    #pragma unroll
    for (int o = 16; o; o >>= 1) s += __shfl_xor_sync(~0u, s, o);
    if (!l) out[b*2 + w] = s + lb[w];
}

extern "C" void kernel_launch(void* const* d_in, const int* in_sizes, int n_in,
                              void* d_out, int out_size) {
    const int*   x    = (const int*)d_in[0];
    const float* emb  = (const float*)d_in[5];
    const float* wihf = (const float*)d_in[6];
    const float* whhf = (const float*)d_in[7];
    const float* bihf = (const float*)d_in[8];
    const float* bhhf = (const float*)d_in[9];
    const float* wihb = (const float*)d_in[10];
    const float* whhb = (const float*)d_in[11];
    const float* bihb = (const float*)d_in[12];
    const float* bhhb = (const float*)d_in[13];
    const float* gam  = (const float*)d_in[14];
    const float* bet  = (const float*)d_in[15];
    const float* mw   = (const float*)d_in[16];
    const float* mb   = (const float*)d_in[17];
    const float* lw   = (const float*)d_in[18];
    const float* lb   = (const float*)d_in[19];
    float* out = (float*)d_out;

    cudaFuncSetAttribute(gemm3, cudaFuncAttributeMaxDynamicSharedMemorySize, 81920);

    prep_w<<<2*DG, DKE>>>(wihf, whhf, wihb, whhb);
    prep_bias<<<6, 256>>>(bihf, bihb, bhhf, bhhb);
    prep_mlp<<<DC2, DC2>>>(mw);
    pad_projk<<<2*DG, 128>>>(wihf, wihb, emb);
    gather_emb<<<DM, DKE>>>(x, emb);

    gemm3<<<dim3(DM/128, DG/128, 2), 256, 81920>>>(0);   // proj fp16 (+bih), 1-term
    gru_update<<<dim3(DM,2), 128>>>(-14, 14, 0);
    for (int i = 1; i < 15; ++i) {
        gemm3<<<dim3(DM/128, DG/128, 2), 256, 81920>>>(1);   // hg fp16 (+bhh), 1-term
        gru_update<<<dim3(DM,2), 128>>>(i - 14, 14 - i, 1);
    }
    concat_stats<<<128, 256>>>(x);
    bn_fin<<<1, DC2>>>(gam, bet);
    norm_split<<<DM, DC2>>>(x);
    gemm3<<<dim3(DM/128, DC2/128, 1), 256, 81920>>>(2);  // MLP fp32, 3-term
    poolk<<<32, DC2>>>(x, mb);
    headk<<<32, 64>>>(lw, lb, out);
}